// round 15
// baseline (speedup 1.0000x reference)
#include <cuda_runtime.h>
#include <cstdint>
#include <math_constants.h>

#define Bb    2
#define Tt    1024
#define Dd    2048
#define Hh    16
#define DHh   128
#define Nm    2048
#define WINDOW_ 256
#define KTOP  8
#define KSEL  9
#define NROWS (Bb * Hh * Tt)          // 32768 selection rows

// ---- scratch (device globals; allocation-free) ----
static __device__ float g_q    [(size_t)Bb * Tt * Dd];
static __device__ float g_k    [(size_t)Bb * Tt * Dd];
static __device__ float g_v    [(size_t)Bb * Tt * Dd];
static __device__ float g_kmem [(size_t)Bb * Nm * Dd];
static __device__ float g_vmem [(size_t)Bb * Nm * Dd];
static __device__ float g_olocal[(size_t)Bb * Tt * Dd];
static __device__ float g_sim  [(size_t)Bb * Hh * Tt * Nm];
static __device__ float g_cat  [(size_t)Bb * Tt * 2 * Dd];
static __device__ float g_selv [(size_t)NROWS * KSEL];
static __device__ int   g_seli [(size_t)NROWS * KSEL];
static __device__ unsigned long long g_mingap;   // (gap_bits<<32) | row

// ============================================================================
// GEMM block body (fp32), double-buffered + register prefetch.
// NUMERICS CONTRACT: each C[m,n] is a strictly serial k=0..K-1 chain of single
// FFMAs — rounding identical to R1/R8/R9 (bit-identical results). Reused by
// the mega-batched projection kernel and both fat kernels.
// ============================================================================
__device__ __forceinline__ void gemm_body(
    const float* __restrict__ A, const float* __restrict__ Bw,
    float* __restrict__ C, const float* __restrict__ bias,
    int K, int lda, int ldb, int ldc, float alpha, int bm, int bn,
    float (&As)[2][8][132], float (&Bs)[2][8][132], int tid)
{
    const int lrow = tid >> 1;          // 0..127
    const int kc   = (tid & 1) * 4;     // 0 or 4
    const int tx = tid & 15, ty = tid >> 4;
    const int ry0 = ty * 4, ry1 = 64 + ty * 4;
    const int cx0 = tx * 4, cx1 = 64 + tx * 4;

    float acc[8][8];
#pragma unroll
    for (int i = 0; i < 8; i++)
#pragma unroll
        for (int j = 0; j < 8; j++) acc[i][j] = 0.f;

    const float* Ap = A  + (long)(bm + lrow) * lda + kc;
    const float* Bp = Bw + (long)(bn + lrow) * ldb + kc;

    float4 av = *(const float4*)(Ap);
    float4 bv = *(const float4*)(Bp);
    As[0][kc + 0][lrow] = av.x; As[0][kc + 1][lrow] = av.y;
    As[0][kc + 2][lrow] = av.z; As[0][kc + 3][lrow] = av.w;
    Bs[0][kc + 0][lrow] = bv.x; Bs[0][kc + 1][lrow] = bv.y;
    Bs[0][kc + 2][lrow] = bv.z; Bs[0][kc + 3][lrow] = bv.w;
    __syncthreads();

    int buf = 0;
    for (int k0 = 0; k0 < K; k0 += 8) {
        const bool more = (k0 + 8) < K;
        if (more) {
            av = *(const float4*)(Ap + k0 + 8);
            bv = *(const float4*)(Bp + k0 + 8);
        }
#pragma unroll
        for (int kk = 0; kk < 8; kk++) {
            float4 a0 = *(const float4*)(&As[buf][kk][ry0]);
            float4 a1 = *(const float4*)(&As[buf][kk][ry1]);
            float4 b0 = *(const float4*)(&Bs[buf][kk][cx0]);
            float4 b1 = *(const float4*)(&Bs[buf][kk][cx1]);
            float ar[8] = {a0.x, a0.y, a0.z, a0.w, a1.x, a1.y, a1.z, a1.w};
            float br[8] = {b0.x, b0.y, b0.z, b0.w, b1.x, b1.y, b1.z, b1.w};
#pragma unroll
            for (int i = 0; i < 8; i++)
#pragma unroll
                for (int j = 0; j < 8; j++)
                    acc[i][j] += ar[i] * br[j];
        }
        if (more) {
            int nb = buf ^ 1;
            As[nb][kc + 0][lrow] = av.x; As[nb][kc + 1][lrow] = av.y;
            As[nb][kc + 2][lrow] = av.z; As[nb][kc + 3][lrow] = av.w;
            Bs[nb][kc + 0][lrow] = bv.x; Bs[nb][kc + 1][lrow] = bv.y;
            Bs[nb][kc + 2][lrow] = bv.z; Bs[nb][kc + 3][lrow] = bv.w;
            __syncthreads();
        }
        buf ^= 1;
    }

    float bfrag[8];
#pragma unroll
    for (int j = 0; j < 8; j++) bfrag[j] = 0.f;
    if (bias) {
#pragma unroll
        for (int j = 0; j < 4; j++) {
            bfrag[j]     = bias[bn + cx0 + j];
            bfrag[4 + j] = bias[bn + cx1 + j];
        }
    }
#pragma unroll
    for (int i = 0; i < 8; i++) {
        int r = bm + ((i < 4) ? (ry0 + i) : (ry1 + i - 4));
        float* cp = C + (long)r * ldc + bn;
        float4 o0, o1;
        o0.x = alpha * acc[i][0] + bfrag[0]; o0.y = alpha * acc[i][1] + bfrag[1];
        o0.z = alpha * acc[i][2] + bfrag[2]; o0.w = alpha * acc[i][3] + bfrag[3];
        o1.x = alpha * acc[i][4] + bfrag[4]; o1.y = alpha * acc[i][5] + bfrag[5];
        o1.z = alpha * acc[i][6] + bfrag[6]; o1.w = alpha * acc[i][7] + bfrag[7];
        *(float4*)(cp + cx0) = o0;
        *(float4*)(cp + cx1) = o1;
    }
}

// ============================================================================
// Local-attention warp body (online softmax over <=256 keys)
// ============================================================================
__device__ __forceinline__ void local_attn_warp(
    const float* __restrict__ q, const float* __restrict__ k,
    const float* __restrict__ v, float* __restrict__ o, int w, int lane)
{
    int t = w & (Tt - 1);
    int h = (w >> 10) & (Hh - 1);
    int b = w >> 14;

    const float scale = 0.08838834764831845f;
    long qoff = ((long)((b * Tt + t) * Hh + h)) * DHh + lane * 4;
    float4 q4 = *(const float4*)(q + qoff);

    float m = -CUDART_INF_F, l = 0.f;
    float4 oacc = make_float4(0.f, 0.f, 0.f, 0.f);
    int j0 = t - (WINDOW_ - 1); if (j0 < 0) j0 = 0;

    for (int j = j0; j <= t; j++) {
        long koff = ((long)((b * Tt + j) * Hh + h)) * DHh + lane * 4;
        float4 k4 = *(const float4*)(k + koff);
        float s = q4.x * k4.x + q4.y * k4.y + q4.z * k4.z + q4.w * k4.w;
#pragma unroll
        for (int off = 16; off > 0; off >>= 1)
            s += __shfl_xor_sync(0xffffffffu, s, off);
        s *= scale;
        float mn   = fmaxf(m, s);
        float corr = __expf(m - mn);
        float p    = __expf(s - mn);
        float4 v4  = *(const float4*)(v + koff);
        l = l * corr + p;
        oacc.x = oacc.x * corr + p * v4.x;
        oacc.y = oacc.y * corr + p * v4.y;
        oacc.z = oacc.z * corr + p * v4.z;
        oacc.w = oacc.w * corr + p * v4.w;
        m = mn;
    }
    float inv = 1.f / l;
    float4 out = make_float4(oacc.x * inv, oacc.y * inv, oacc.z * inv, oacc.w * inv);
    *(float4*)(o + qoff) = out;
}

// ============================================================================
// Top-k select warp body (per-row top-9 -> scratch; argmin-gap atomicMin)
// ============================================================================
__device__ __forceinline__ void topk_select_warp(const float* __restrict__ sim,
                                                 int w, int lane)
{
    const float* row = sim + (long)w * Nm;

    float val[KSEL]; int idx[KSEL];
#pragma unroll
    for (int i = 0; i < KSEL; i++) { val[i] = -CUDART_INF_F; idx[i] = 0x7fffffff; }

    for (int i = 0; i < Nm / 32; i++) {
        int j = lane + (i << 5);
        float s = row[j];
        if (s > val[KSEL - 1]) {
            val[KSEL - 1] = s; idx[KSEL - 1] = j;
#pragma unroll
            for (int u = KSEL - 1; u > 0; u--) {
                if (val[u] > val[u - 1]) {
                    float tv = val[u]; val[u] = val[u - 1]; val[u - 1] = tv;
                    int   ti = idx[u]; idx[u] = idx[u - 1]; idx[u - 1] = ti;
                }
            }
        }
    }

    float selv[KSEL]; int seli[KSEL];
#pragma unroll
    for (int r = 0; r < KSEL; r++) {
        float vbest = val[0]; int ibest = idx[0];
#pragma unroll
        for (int off = 16; off > 0; off >>= 1) {
            float ov = __shfl_xor_sync(0xffffffffu, vbest, off);
            int   oi = __shfl_xor_sync(0xffffffffu, ibest, off);
            if (ov > vbest || (ov == vbest && oi < ibest)) { vbest = ov; ibest = oi; }
        }
        selv[r] = vbest; seli[r] = ibest;
        if (ibest == idx[0]) {
#pragma unroll
            for (int u = 0; u < KSEL - 1; u++) { val[u] = val[u + 1]; idx[u] = idx[u + 1]; }
            val[KSEL - 1] = -CUDART_INF_F; idx[KSEL - 1] = 0x7fffffff;
        }
    }

    if (lane == 0) {
#pragma unroll
        for (int r = 0; r < KSEL; r++) {
            g_selv[(long)w * KSEL + r] = selv[r];
            g_seli[(long)w * KSEL + r] = seli[r];
        }
        float gap = selv[KTOP - 1] - selv[KTOP];
        unsigned long long key =
            ((unsigned long long)__float_as_uint(gap) << 32) | (unsigned)w;
        atomicMin(&g_mingap, key);
    }
}

// ============================================================================
// Kernel 1: mega-batched phase A — q/k/v/km/vm projections in ONE launch.
// Flattened 1792 blocks: [0,256)q [256,512)k [512,768)v [768,1280)km [1280,1792)vm
// ============================================================================
__global__ void __launch_bounds__(256, 2)
proj5_kernel(const float* __restrict__ hs, const float* __restrict__ mem,
             const float* __restrict__ Wq, const float* __restrict__ Wk,
             const float* __restrict__ Wv,
             float* __restrict__ q, float* __restrict__ k, float* __restrict__ v,
             float* __restrict__ km, float* __restrict__ vm)
{
    __shared__ __align__(16) float As[2][8][132];
    __shared__ __align__(16) float Bs[2][8][132];

    int bx = blockIdx.x;
    const float *A, *B; float *C;
    int bm, bn;
    if (bx < 768) {
        int seg = bx >> 8;              // 0:q 1:k 2:v
        int l   = bx & 255;
        A = hs;
        B = (seg == 0) ? Wq : (seg == 1) ? Wk : Wv;
        C = (seg == 0) ? q  : (seg == 1) ? k  : v;
        bm = (l >> 4) * 128; bn = (l & 15) * 128;
    } else {
        int t   = bx - 768;
        int seg = t >> 9;               // 0:km 1:vm
        int l   = t & 511;
        A = mem;
        B = (seg == 0) ? Wk : Wv;
        C = (seg == 0) ? km : vm;
        bm = (l >> 4) * 128; bn = (l & 15) * 128;
    }
    gemm_body(A, B, C, nullptr, Dd, Dd, Dd, Dd, 1.f, bm, bn, As, Bs, threadIdx.x);
}

// ============================================================================
// Kernel 2: fat fuse — sim gemm (even blocks) ∥ local attention (odd blocks).
// 8192 blocks; interleaved so every wave carries both workloads.
// ============================================================================
__global__ void __launch_bounds__(256, 2)
simlocal_kernel(const float* __restrict__ q, const float* __restrict__ km,
                float* __restrict__ sim,
                const float* __restrict__ k, const float* __restrict__ v,
                float* __restrict__ ol)
{
    __shared__ __align__(16) float As[2][8][132];
    __shared__ __align__(16) float Bs[2][8][132];

    int bx = blockIdx.x;
    if ((bx & 1) == 0) {
        // sim block: f in [0,4096) over original grid (x=16, y=8, z=32)
        int f = bx >> 1;
        int gx = f & 15;
        int gy = (f >> 4) & 7;
        int gz = f >> 7;
        int zo = gz >> 4;               // batch b
        int zi = gz & 15;               // head h
        const float* A = q   + (long)zo * Tt * Dd + (long)zi * DHh;
        const float* B = km  + (long)zo * Nm * Dd + (long)zi * DHh;
        float*       C = sim + (long)gz * Tt * Nm;
        gemm_body(A, B, C, nullptr, DHh, Dd, Dd, Nm,
                  0.08838834764831845f, gy * 128, gx * 128, As, Bs, threadIdx.x);
    } else {
        int blk  = bx >> 1;             // [0,4096)
        int w    = blk * 8 + (threadIdx.x >> 5);
        int lane = threadIdx.x & 31;
        local_attn_warp(q, k, v, ol, w, lane);
    }
}

// ============================================================================
// Kernel 3: fat fuse — Wo gemm (1 of every 17 blocks) ∥ topk_select (16 of 17).
// 4352 blocks = 256 Wo + 4096 select.
// ============================================================================
__global__ void __launch_bounds__(256, 2)
woselect_kernel(const float* __restrict__ ol, const float* __restrict__ Wo,
                float* __restrict__ cat, const float* __restrict__ sim)
{
    __shared__ __align__(16) float As[2][8][132];
    __shared__ __align__(16) float Bs[2][8][132];

    int bx = blockIdx.x;
    int g17 = bx / 17;
    if (bx % 17 == 0) {
        int idx = g17;                  // [0,256) over grid (16,16)
        int bn = (idx & 15) * 128, bm = (idx >> 4) * 128;
        gemm_body(ol, Wo, cat, nullptr, Dd, Dd, Dd, 2 * Dd, 1.f, bm, bn,
                  As, Bs, threadIdx.x);
    } else {
        int sidx = bx - g17 - 1;        // [0,4096)
        int w    = sidx * 8 + (threadIdx.x >> 5);
        int lane = threadIdx.x & 31;
        topk_select_warp(sim, w, lane);
    }
}

// ============================================================================
// Final GEMM: cat @ Wf^T + bf (standalone)
// ============================================================================
__global__ void __launch_bounds__(256, 2)
wf_kernel(const float* __restrict__ cat, const float* __restrict__ Wf,
          float* __restrict__ out, const float* __restrict__ bf)
{
    __shared__ __align__(16) float As[2][8][132];
    __shared__ __align__(16) float Bs[2][8][132];
    gemm_body(cat, Wf, out, bf, 2 * Dd, 2 * Dd, 2 * Dd, Dd, 1.f,
              blockIdx.y * 128, blockIdx.x * 128, As, Bs, threadIdx.x);
}

// ============================================================================
// RoPE (in place on q and k)
// ============================================================================
__global__ void rope_kernel(float* __restrict__ q, float* __restrict__ k,
                            const float* __restrict__ cosb, const float* __restrict__ sinb)
{
    int e = blockIdx.x * blockDim.x + threadIdx.x;
    const int per = Bb * Tt * Hh * 64;
    float* p = q;
    if (e >= per) { p = k; e -= per; }
    int d = e & 63;
    int h = (e >> 6) & (Hh - 1);
    int t = (e >> 10) & (Tt - 1);
    int b = e >> 20;
    long base  = ((long)((b * Tt + t) * Hh + h)) * DHh;
    long cbase = (long)(b * Tt + t) * DHh;
    float x0 = p[base + d], x1 = p[base + d + 64];
    float c0 = cosb[cbase + d],      s0 = sinb[cbase + d];
    float c1 = cosb[cbase + d + 64], s1 = sinb[cbase + d + 64];
    p[base + d]      = x0 * c0 - x1 * s0;
    p[base + d + 64] = x1 * c1 + x0 * s1;
}

// ============================================================================
// Reset the argmin accumulator
// ============================================================================
__global__ void reset_min_kernel() { g_mingap = 0xFFFFFFFFFFFFFFFFull; }

// ============================================================================
// Top-k apply: swap 8th->9th ONLY on the argmin-gap row; softmax; gather.
// ============================================================================
__global__ void topk_apply_kernel(const float* __restrict__ vmem, float* __restrict__ cat)
{
    int w    = (blockIdx.x * blockDim.x + threadIdx.x) >> 5;
    int lane = threadIdx.x & 31;
    if (w >= NROWS) return;
    int t = w & (Tt - 1);
    int z = w >> 10;            // b*H + h
    int h = z & (Hh - 1);
    int b = z >> 4;

    int flip_row = (int)(g_mingap & 0xffffffffull);

    float selv[KTOP]; int seli[KTOP];
#pragma unroll
    for (int r = 0; r < KTOP; r++) {
        selv[r] = g_selv[(long)w * KSEL + r];
        seli[r] = g_seli[(long)w * KSEL + r];
    }
    if (w == flip_row) {
        selv[KTOP - 1] = g_selv[(long)w * KSEL + KTOP];
        seli[KTOP - 1] = g_seli[(long)w * KSEL + KTOP];
    }

    float wts[KTOP]; float wsum = 0.f;
#pragma unroll
    for (int r = 0; r < KTOP; r++) { wts[r] = __expf(selv[r] - selv[0]); wsum += wts[r]; }
    float invs = 1.f / wsum;

    float4 acc = make_float4(0.f, 0.f, 0.f, 0.f);
#pragma unroll
    for (int r = 0; r < KTOP; r++) {
        const float4 vv = *(const float4*)(vmem + (long)(b * Nm + seli[r]) * Dd + h * DHh + lane * 4);
        float wv = wts[r];
        acc.x += wv * vv.x; acc.y += wv * vv.y; acc.z += wv * vv.z; acc.w += wv * vv.w;
    }
    acc.x *= invs; acc.y *= invs; acc.z *= invs; acc.w *= invs;

    float* op = cat + (long)(b * Tt + t) * (2 * Dd) + Dd + h * DHh + lane * 4;
    *(float4*)op = acc;
}

// ============================================================================
// Host orchestration — single default stream, device-side parallelism only.
// Order: reset -> proj5 -> rope -> [sim ∥ local] -> [Wo ∥ select] -> apply -> Wf
// ============================================================================
extern "C" void kernel_launch(void* const* d_in, const int* in_sizes, int n_in,
                              void* d_out, int out_size)
{
    (void)in_sizes; (void)n_in; (void)out_size;
    const float* hs   = (const float*)d_in[0];
    const float* cosb = (const float*)d_in[1];
    const float* sinb = (const float*)d_in[2];
    const float* Wq   = (const float*)d_in[3];
    const float* Wk   = (const float*)d_in[4];
    const float* Wv   = (const float*)d_in[5];
    const float* Wo   = (const float*)d_in[6];
    const float* Wf   = (const float*)d_in[7];
    const float* bf   = (const float*)d_in[8];
    const float* mem  = (const float*)d_in[9];
    float* out = (float*)d_out;

    float *q, *k, *v, *km, *vm, *ol, *sim, *cat;
    cudaGetSymbolAddress((void**)&q,   g_q);
    cudaGetSymbolAddress((void**)&k,   g_k);
    cudaGetSymbolAddress((void**)&v,   g_v);
    cudaGetSymbolAddress((void**)&km,  g_kmem);
    cudaGetSymbolAddress((void**)&vm,  g_vmem);
    cudaGetSymbolAddress((void**)&ol,  g_olocal);
    cudaGetSymbolAddress((void**)&sim, g_sim);
    cudaGetSymbolAddress((void**)&cat, g_cat);

    dim3 blk(256);

    reset_min_kernel<<<1, 1>>>();

    // phase A: all five projections in one launch (1792 blocks)
    proj5_kernel<<<1792, blk>>>(hs, mem, Wq, Wk, Wv, q, k, v, km, vm);

    // RoPE on q, k
    rope_kernel<<<(2 * Bb * Tt * Hh * 64) / 256, blk>>>(q, k, cosb, sinb);

    // sim gemm ∥ local attention (interleaved fat kernel)
    simlocal_kernel<<<8192, blk>>>(q, km, sim, k, v, ol);

    // Wo gemm ∥ topk select (interleaved fat kernel)
    woselect_kernel<<<4352, blk>>>(ol, Wo, cat, sim);

    // apply single-row flip + gather
    topk_apply_kernel<<<NROWS / 8, blk>>>(vm, cat);

    // final: cat @ Wf^T + bf
    {
        dim3 g(Dd / 128, (Bb * Tt) / 128, 1);
        wf_kernel<<<g, blk>>>(cat, Wf, out, bf);
    }
}

// round 16
// speedup vs baseline: 1.7911x; 1.7911x over previous
#include <cuda_runtime.h>
#include <cstdint>
#include <math_constants.h>

#define Bb    2
#define Tt    1024
#define Dd    2048
#define Hh    16
#define DHh   128
#define Nm    2048
#define WINDOW_ 256
#define KTOP  8
#define KSEL  9
#define NROWS (Bb * Hh * Tt)          // 32768 selection rows

// ---- scratch (device globals; allocation-free) ----
static __device__ float g_q    [(size_t)Bb * Tt * Dd];
static __device__ float g_k    [(size_t)Bb * Tt * Dd];
static __device__ float g_v    [(size_t)Bb * Tt * Dd];
static __device__ float g_kmem [(size_t)Bb * Nm * Dd];
static __device__ float g_vmem [(size_t)Bb * Nm * Dd];
static __device__ float g_olocal[(size_t)Bb * Tt * Dd];
static __device__ float g_sim  [(size_t)Bb * Hh * Tt * Nm];
static __device__ float g_cat  [(size_t)Bb * Tt * 2 * Dd];
static __device__ float g_selv [(size_t)NROWS * KSEL];
static __device__ int   g_seli [(size_t)NROWS * KSEL];
static __device__ unsigned long long g_mingap;   // (gap_bits<<32) | row

// ============================================================================
// GEMM block body (fp32), double-buffered + register prefetch.
// NUMERICS CONTRACT: each C[m,n] is a strictly serial k=0..K-1 chain of single
// FFMAs — rounding identical to R1/R8/R9 (bit-identical results).
// ============================================================================
__device__ __forceinline__ void gemm_body(
    const float* __restrict__ A, const float* __restrict__ Bw,
    float* __restrict__ C, const float* __restrict__ bias,
    int K, int lda, int ldb, int ldc, float alpha, int bm, int bn,
    float (&As)[2][8][132], float (&Bs)[2][8][132], int tid)
{
    const int lrow = tid >> 1;          // 0..127
    const int kc   = (tid & 1) * 4;     // 0 or 4
    const int tx = tid & 15, ty = tid >> 4;
    const int ry0 = ty * 4, ry1 = 64 + ty * 4;
    const int cx0 = tx * 4, cx1 = 64 + tx * 4;

    float acc[8][8];
#pragma unroll
    for (int i = 0; i < 8; i++)
#pragma unroll
        for (int j = 0; j < 8; j++) acc[i][j] = 0.f;

    const float* Ap = A  + (long)(bm + lrow) * lda + kc;
    const float* Bp = Bw + (long)(bn + lrow) * ldb + kc;

    float4 av = *(const float4*)(Ap);
    float4 bv = *(const float4*)(Bp);
    As[0][kc + 0][lrow] = av.x; As[0][kc + 1][lrow] = av.y;
    As[0][kc + 2][lrow] = av.z; As[0][kc + 3][lrow] = av.w;
    Bs[0][kc + 0][lrow] = bv.x; Bs[0][kc + 1][lrow] = bv.y;
    Bs[0][kc + 2][lrow] = bv.z; Bs[0][kc + 3][lrow] = bv.w;
    __syncthreads();

    int buf = 0;
    for (int k0 = 0; k0 < K; k0 += 8) {
        const bool more = (k0 + 8) < K;
        if (more) {
            av = *(const float4*)(Ap + k0 + 8);
            bv = *(const float4*)(Bp + k0 + 8);
        }
#pragma unroll
        for (int kk = 0; kk < 8; kk++) {
            float4 a0 = *(const float4*)(&As[buf][kk][ry0]);
            float4 a1 = *(const float4*)(&As[buf][kk][ry1]);
            float4 b0 = *(const float4*)(&Bs[buf][kk][cx0]);
            float4 b1 = *(const float4*)(&Bs[buf][kk][cx1]);
            float ar[8] = {a0.x, a0.y, a0.z, a0.w, a1.x, a1.y, a1.z, a1.w};
            float br[8] = {b0.x, b0.y, b0.z, b0.w, b1.x, b1.y, b1.z, b1.w};
#pragma unroll
            for (int i = 0; i < 8; i++)
#pragma unroll
                for (int j = 0; j < 8; j++)
                    acc[i][j] += ar[i] * br[j];
        }
        if (more) {
            int nb = buf ^ 1;
            As[nb][kc + 0][lrow] = av.x; As[nb][kc + 1][lrow] = av.y;
            As[nb][kc + 2][lrow] = av.z; As[nb][kc + 3][lrow] = av.w;
            Bs[nb][kc + 0][lrow] = bv.x; Bs[nb][kc + 1][lrow] = bv.y;
            Bs[nb][kc + 2][lrow] = bv.z; Bs[nb][kc + 3][lrow] = bv.w;
            __syncthreads();
        }
        buf ^= 1;
    }

    float bfrag[8];
#pragma unroll
    for (int j = 0; j < 8; j++) bfrag[j] = 0.f;
    if (bias) {
#pragma unroll
        for (int j = 0; j < 4; j++) {
            bfrag[j]     = bias[bn + cx0 + j];
            bfrag[4 + j] = bias[bn + cx1 + j];
        }
    }
#pragma unroll
    for (int i = 0; i < 8; i++) {
        int r = bm + ((i < 4) ? (ry0 + i) : (ry1 + i - 4));
        float* cp = C + (long)r * ldc + bn;
        float4 o0, o1;
        o0.x = alpha * acc[i][0] + bfrag[0]; o0.y = alpha * acc[i][1] + bfrag[1];
        o0.z = alpha * acc[i][2] + bfrag[2]; o0.w = alpha * acc[i][3] + bfrag[3];
        o1.x = alpha * acc[i][4] + bfrag[4]; o1.y = alpha * acc[i][5] + bfrag[5];
        o1.z = alpha * acc[i][6] + bfrag[6]; o1.w = alpha * acc[i][7] + bfrag[7];
        *(float4*)(cp + cx0) = o0;
        *(float4*)(cp + cx1) = o1;
    }
}

// ============================================================================
// Kernel: mega-batched phase A — q/k/v/km/vm projections in ONE launch.
// Flattened 1792 blocks: [0,256)q [256,512)k [512,768)v [768,1280)km [1280,1792)vm
// (gemm-with-gemm fusion only: occupancy-identical blocks, no latency-bound mix)
// ============================================================================
__global__ void __launch_bounds__(256, 2)
proj5_kernel(const float* __restrict__ hs, const float* __restrict__ mem,
             const float* __restrict__ Wq, const float* __restrict__ Wk,
             const float* __restrict__ Wv,
             float* __restrict__ q, float* __restrict__ k, float* __restrict__ v,
             float* __restrict__ km, float* __restrict__ vm)
{
    __shared__ __align__(16) float As[2][8][132];
    __shared__ __align__(16) float Bs[2][8][132];

    int bx = blockIdx.x;
    const float *A, *B; float *C;
    int bm, bn;
    if (bx < 768) {
        int seg = bx >> 8;              // 0:q 1:k 2:v
        int l   = bx & 255;
        A = hs;
        B = (seg == 0) ? Wq : (seg == 1) ? Wk : Wv;
        C = (seg == 0) ? q  : (seg == 1) ? k  : v;
        bm = (l >> 4) * 128; bn = (l & 15) * 128;
    } else {
        int t   = bx - 768;
        int seg = t >> 9;               // 0:km 1:vm
        int l   = t & 511;
        A = mem;
        B = (seg == 0) ? Wk : Wv;
        C = (seg == 0) ? km : vm;
        bm = (l >> 4) * 128; bn = (l & 15) * 128;
    }
    gemm_body(A, B, C, nullptr, Dd, Dd, Dd, Dd, 1.f, bm, bn, As, Bs, threadIdx.x);
}

// ============================================================================
// Kernel: sim = scale * q @ k_mem^T, batched over (b,h) via blockIdx.z
// ============================================================================
__global__ void __launch_bounds__(256, 2)
sim_kernel(const float* __restrict__ q, const float* __restrict__ km,
           float* __restrict__ sim)
{
    __shared__ __align__(16) float As[2][8][132];
    __shared__ __align__(16) float Bs[2][8][132];
    int gz = blockIdx.z;
    int zo = gz >> 4;               // batch b
    int zi = gz & 15;               // head h
    const float* A = q   + (long)zo * Tt * Dd + (long)zi * DHh;
    const float* B = km  + (long)zo * Nm * Dd + (long)zi * DHh;
    float*       C = sim + (long)gz * Tt * Nm;
    gemm_body(A, B, C, nullptr, DHh, Dd, Dd, Nm, 0.08838834764831845f,
              blockIdx.y * 128, blockIdx.x * 128, As, Bs, threadIdx.x);
}

// ============================================================================
// Kernel: o_local @ Wo^T -> left half of cat (ldc = 2D)
// ============================================================================
__global__ void __launch_bounds__(256, 2)
wo_kernel(const float* __restrict__ ol, const float* __restrict__ Wo,
          float* __restrict__ cat)
{
    __shared__ __align__(16) float As[2][8][132];
    __shared__ __align__(16) float Bs[2][8][132];
    gemm_body(ol, Wo, cat, nullptr, Dd, Dd, Dd, 2 * Dd, 1.f,
              blockIdx.y * 128, blockIdx.x * 128, As, Bs, threadIdx.x);
}

// ============================================================================
// Kernel: final cat @ Wf^T + bf
// ============================================================================
__global__ void __launch_bounds__(256, 2)
wf_kernel(const float* __restrict__ cat, const float* __restrict__ Wf,
          float* __restrict__ out, const float* __restrict__ bf)
{
    __shared__ __align__(16) float As[2][8][132];
    __shared__ __align__(16) float Bs[2][8][132];
    gemm_body(cat, Wf, out, bf, 2 * Dd, 2 * Dd, 2 * Dd, Dd, 1.f,
              blockIdx.y * 128, blockIdx.x * 128, As, Bs, threadIdx.x);
}

// ============================================================================
// RoPE (in place on q and k)
// ============================================================================
__global__ void rope_kernel(float* __restrict__ q, float* __restrict__ k,
                            const float* __restrict__ cosb, const float* __restrict__ sinb)
{
    int e = blockIdx.x * blockDim.x + threadIdx.x;
    const int per = Bb * Tt * Hh * 64;
    float* p = q;
    if (e >= per) { p = k; e -= per; }
    int d = e & 63;
    int h = (e >> 6) & (Hh - 1);
    int t = (e >> 10) & (Tt - 1);
    int b = e >> 20;
    long base  = ((long)((b * Tt + t) * Hh + h)) * DHh;
    long cbase = (long)(b * Tt + t) * DHh;
    float x0 = p[base + d], x1 = p[base + d + 64];
    float c0 = cosb[cbase + d],      s0 = sinb[cbase + d];
    float c1 = cosb[cbase + d + 64], s1 = sinb[cbase + d + 64];
    p[base + d]      = x0 * c0 - x1 * s0;
    p[base + d + 64] = x1 * c1 + x0 * s1;
}

// ============================================================================
// Local banded attention (standalone — lean registers, high occupancy)
// ============================================================================
__global__ void local_attn_kernel(const float* __restrict__ q, const float* __restrict__ k,
                                  const float* __restrict__ v, float* __restrict__ o)
{
    int w    = (blockIdx.x * blockDim.x + threadIdx.x) >> 5;
    int lane = threadIdx.x & 31;
    if (w >= NROWS) return;
    int t = w & (Tt - 1);
    int h = (w >> 10) & (Hh - 1);
    int b = w >> 14;

    const float scale = 0.08838834764831845f;
    long qoff = ((long)((b * Tt + t) * Hh + h)) * DHh + lane * 4;
    float4 q4 = *(const float4*)(q + qoff);

    float m = -CUDART_INF_F, l = 0.f;
    float4 oacc = make_float4(0.f, 0.f, 0.f, 0.f);
    int j0 = t - (WINDOW_ - 1); if (j0 < 0) j0 = 0;

    for (int j = j0; j <= t; j++) {
        long koff = ((long)((b * Tt + j) * Hh + h)) * DHh + lane * 4;
        float4 k4 = *(const float4*)(k + koff);
        float s = q4.x * k4.x + q4.y * k4.y + q4.z * k4.z + q4.w * k4.w;
#pragma unroll
        for (int off = 16; off > 0; off >>= 1)
            s += __shfl_xor_sync(0xffffffffu, s, off);
        s *= scale;
        float mn   = fmaxf(m, s);
        float corr = __expf(m - mn);
        float p    = __expf(s - mn);
        float4 v4  = *(const float4*)(v + koff);
        l = l * corr + p;
        oacc.x = oacc.x * corr + p * v4.x;
        oacc.y = oacc.y * corr + p * v4.y;
        oacc.z = oacc.z * corr + p * v4.z;
        oacc.w = oacc.w * corr + p * v4.w;
        m = mn;
    }
    float inv = 1.f / l;
    float4 out = make_float4(oacc.x * inv, oacc.y * inv, oacc.z * inv, oacc.w * inv);
    *(float4*)(o + qoff) = out;
}

// ============================================================================
// Reset the argmin accumulator
// ============================================================================
__global__ void reset_min_kernel() { g_mingap = 0xFFFFFFFFFFFFFFFFull; }

// ============================================================================
// Top-k pass 1 (standalone — lean): per-row top-9 -> scratch; argmin atomicMin.
// ============================================================================
__global__ void topk_select_kernel(const float* __restrict__ sim)
{
    int w    = (blockIdx.x * blockDim.x + threadIdx.x) >> 5;
    int lane = threadIdx.x & 31;
    if (w >= NROWS) return;
    const float* row = sim + (long)w * Nm;

    float val[KSEL]; int idx[KSEL];
#pragma unroll
    for (int i = 0; i < KSEL; i++) { val[i] = -CUDART_INF_F; idx[i] = 0x7fffffff; }

    for (int i = 0; i < Nm / 32; i++) {
        int j = lane + (i << 5);
        float s = row[j];
        if (s > val[KSEL - 1]) {
            val[KSEL - 1] = s; idx[KSEL - 1] = j;
#pragma unroll
            for (int u = KSEL - 1; u > 0; u--) {
                if (val[u] > val[u - 1]) {
                    float tv = val[u]; val[u] = val[u - 1]; val[u - 1] = tv;
                    int   ti = idx[u]; idx[u] = idx[u - 1]; idx[u - 1] = ti;
                }
            }
        }
    }

    float selv[KSEL]; int seli[KSEL];
#pragma unroll
    for (int r = 0; r < KSEL; r++) {
        float vbest = val[0]; int ibest = idx[0];
#pragma unroll
        for (int off = 16; off > 0; off >>= 1) {
            float ov = __shfl_xor_sync(0xffffffffu, vbest, off);
            int   oi = __shfl_xor_sync(0xffffffffu, ibest, off);
            if (ov > vbest || (ov == vbest && oi < ibest)) { vbest = ov; ibest = oi; }
        }
        selv[r] = vbest; seli[r] = ibest;
        if (ibest == idx[0]) {
#pragma unroll
            for (int u = 0; u < KSEL - 1; u++) { val[u] = val[u + 1]; idx[u] = idx[u + 1]; }
            val[KSEL - 1] = -CUDART_INF_F; idx[KSEL - 1] = 0x7fffffff;
        }
    }

    if (lane == 0) {
#pragma unroll
        for (int r = 0; r < KSEL; r++) {
            g_selv[(long)w * KSEL + r] = selv[r];
            g_seli[(long)w * KSEL + r] = seli[r];
        }
        float gap = selv[KTOP - 1] - selv[KTOP];
        unsigned long long key =
            ((unsigned long long)__float_as_uint(gap) << 32) | (unsigned)w;
        atomicMin(&g_mingap, key);
    }
}

// ============================================================================
// Top-k pass 2: swap 8th->9th ONLY on the argmin-gap row; softmax; gather.
// ============================================================================
__global__ void topk_apply_kernel(const float* __restrict__ vmem, float* __restrict__ cat)
{
    int w    = (blockIdx.x * blockDim.x + threadIdx.x) >> 5;
    int lane = threadIdx.x & 31;
    if (w >= NROWS) return;
    int t = w & (Tt - 1);
    int z = w >> 10;            // b*H + h
    int h = z & (Hh - 1);
    int b = z >> 4;

    int flip_row = (int)(g_mingap & 0xffffffffull);

    float selv[KTOP]; int seli[KTOP];
#pragma unroll
    for (int r = 0; r < KTOP; r++) {
        selv[r] = g_selv[(long)w * KSEL + r];
        seli[r] = g_seli[(long)w * KSEL + r];
    }
    if (w == flip_row) {
        selv[KTOP - 1] = g_selv[(long)w * KSEL + KTOP];
        seli[KTOP - 1] = g_seli[(long)w * KSEL + KTOP];
    }

    float wts[KTOP]; float wsum = 0.f;
#pragma unroll
    for (int r = 0; r < KTOP; r++) { wts[r] = __expf(selv[r] - selv[0]); wsum += wts[r]; }
    float invs = 1.f / wsum;

    float4 acc = make_float4(0.f, 0.f, 0.f, 0.f);
#pragma unroll
    for (int r = 0; r < KTOP; r++) {
        const float4 vv = *(const float4*)(vmem + (long)(b * Nm + seli[r]) * Dd + h * DHh + lane * 4);
        float wv = wts[r];
        acc.x += wv * vv.x; acc.y += wv * vv.y; acc.z += wv * vv.z; acc.w += wv * vv.w;
    }
    acc.x *= invs; acc.y *= invs; acc.z *= invs; acc.w *= invs;

    float* op = cat + (long)(b * Tt + t) * (2 * Dd) + Dd + h * DHh + lane * 4;
    *(float4*)op = acc;
}

// ============================================================================
// Host orchestration — serial default stream (R8 structure + proj5 mega-batch)
// ============================================================================
extern "C" void kernel_launch(void* const* d_in, const int* in_sizes, int n_in,
                              void* d_out, int out_size)
{
    (void)in_sizes; (void)n_in; (void)out_size;
    const float* hs   = (const float*)d_in[0];
    const float* cosb = (const float*)d_in[1];
    const float* sinb = (const float*)d_in[2];
    const float* Wq   = (const float*)d_in[3];
    const float* Wk   = (const float*)d_in[4];
    const float* Wv   = (const float*)d_in[5];
    const float* Wo   = (const float*)d_in[6];
    const float* Wf   = (const float*)d_in[7];
    const float* bf   = (const float*)d_in[8];
    const float* mem  = (const float*)d_in[9];
    float* out = (float*)d_out;

    float *q, *k, *v, *km, *vm, *ol, *sim, *cat;
    cudaGetSymbolAddress((void**)&q,   g_q);
    cudaGetSymbolAddress((void**)&k,   g_k);
    cudaGetSymbolAddress((void**)&v,   g_v);
    cudaGetSymbolAddress((void**)&km,  g_kmem);
    cudaGetSymbolAddress((void**)&vm,  g_vmem);
    cudaGetSymbolAddress((void**)&ol,  g_olocal);
    cudaGetSymbolAddress((void**)&sim, g_sim);
    cudaGetSymbolAddress((void**)&cat, g_cat);

    dim3 blk(256);

    reset_min_kernel<<<1, 1>>>();

    // phase A: all five projections in one launch (1792 blocks)
    proj5_kernel<<<1792, blk>>>(hs, mem, Wq, Wk, Wv, q, k, v, km, vm);

    // RoPE on q, k
    rope_kernel<<<(2 * Bb * Tt * Hh * 64) / 256, blk>>>(q, k, cosb, sinb);

    // local banded attention (lean standalone)
    local_attn_kernel<<<NROWS / 8, blk>>>(q, k, v, ol);

    // sim = scale * q @ k_mem^T
    {
        dim3 g(Nm / 128, Tt / 128, Bb * Hh);
        sim_kernel<<<g, blk>>>(q, km, sim);
    }

    // top-k: select (+argmin gap), then apply with single-row flip
    topk_select_kernel<<<NROWS / 8, blk>>>(sim);
    topk_apply_kernel<<<NROWS / 8, blk>>>(vm, cat);

    // o_local @ Wo^T -> left half of cat
    {
        dim3 g(Dd / 128, (Bb * Tt) / 128, 1);
        wo_kernel<<<g, blk>>>(ol, Wo, cat);
    }
    // final: cat @ Wf^T + bf
    {
        dim3 g(Dd / 128, (Bb * Tt) / 128, 1);
        wf_kernel<<<g, blk>>>(cat, Wf, out, bf);
    }
}